// round 4
// baseline (speedup 1.0000x reference)
#include <cuda_runtime.h>

// y[m,n] = sum_k x[m,k] * (mask[n,k]*W[n,k]) + b[n]
// M=16384, K=2048, N=8192, fp32.
//
// Pipeline:
//  1. rowscan:    per output row n, 64-word k-bitmask + heavy flag (>=256 nnz)
//  2. tile_pack:  per 24-wide n-tile, union of non-heavy rows' bitmasks ->
//                 ordered k index list + packed PRE-SPLATTED weight panel
//  3. heavy_list: deterministic ordered list of heavy columns
//  4. transpose:  xT[k][m]  (spmm gather becomes coalesced)
//  5. spmm:       gather GEMM over compacted K; 3-stage cp.async pipeline,
//                 one bar/chunk, f32x2 over m-pairs, LDS.128 only
//  6. dense_cols: recompute heavy columns densely, overwrite their output

#define M_DIM 16384
#define K_DIM 2048
#define N_DIM 8192
#define TN 24
#define NTILES ((N_DIM + TN - 1) / TN)   // 342
#define TM 256
#define KCHUNK 8
#define NSTAGE 3
#define HEAVY_THRESH 256

// Static scratch (allocations are forbidden).
__device__ unsigned g_rowbits[(size_t)N_DIM * 64];            // 2 MB
__device__ int      g_heavyflag[N_DIM];
__device__ int      g_heavy[N_DIM];
__device__ int      g_nheavy;
__device__ int      g_kidx[NTILES * K_DIM];                   // 2.8 MB
__device__ int      g_kpad[NTILES];
__device__ float2   g_Wp2[(size_t)NTILES * K_DIM * TN];       // 134 MB, splatted
__device__ float    g_xT[(size_t)K_DIM * M_DIM];              // 128 MB

// ---------------------------------------------------------------------------
// helpers
// ---------------------------------------------------------------------------
__device__ __forceinline__ void fma2(unsigned long long& acc,
                                     unsigned long long a,
                                     unsigned long long b) {
    asm("fma.rn.f32x2 %0, %1, %2, %0;" : "+l"(acc) : "l"(a), "l"(b));
}
__device__ __forceinline__ void unpack2(unsigned long long a, float& lo, float& hi) {
    asm("mov.b64 {%0, %1}, %2;" : "=f"(lo), "=f"(hi) : "l"(a));
}
__device__ __forceinline__ void cpasync16(unsigned dst, const void* src) {
    asm volatile("cp.async.cg.shared.global [%0], [%1], 16;" :: "r"(dst), "l"(src));
}
__device__ __forceinline__ void cp_commit() { asm volatile("cp.async.commit_group;"); }
template <int N>
__device__ __forceinline__ void cp_wait() { asm volatile("cp.async.wait_group %0;" :: "n"(N)); }

// ---------------------------------------------------------------------------
// 1. Per-row bitmask + heavy flag. One warp per output row.
// ---------------------------------------------------------------------------
__global__ void rowscan_kernel(const float* __restrict__ mask) {
    int warp = (blockIdx.x * blockDim.x + threadIdx.x) >> 5;
    int lane = threadIdx.x & 31;
    if (warp >= N_DIM) return;
    const float* row = mask + (size_t)warp * K_DIM;
    int cnt = 0;
    #pragma unroll 8
    for (int w = 0; w < K_DIM / 32; ++w) {
        float v = row[w * 32 + lane];
        unsigned b = __ballot_sync(0xffffffffu, v != 0.0f);
        if (lane == 0) g_rowbits[(size_t)warp * 64 + w] = b;
        cnt += __popc(b);
    }
    if (lane == 0) g_heavyflag[warp] = (cnt >= HEAVY_THRESH) ? 1 : 0;
}

// ---------------------------------------------------------------------------
// 2. Per n-tile: union bitmask (excluding heavy rows), ordered compaction,
//    packed pre-splatted masked weights.
// ---------------------------------------------------------------------------
__global__ void tile_pack_kernel(const float* __restrict__ W,
                                 const float* __restrict__ mask) {
    const int t = blockIdx.x, n0 = t * TN, tid = threadIdx.x;
    __shared__ unsigned words[64];
    __shared__ int cnts[64];
    __shared__ int hflag[TN];
    __shared__ int s_cnt, s_kpad;

    if (tid < TN)
        hflag[tid] = (n0 + tid < N_DIM) ? g_heavyflag[n0 + tid] : 1;
    __syncthreads();

    if (tid < 64) {
        unsigned u = 0;
        #pragma unroll 4
        for (int nn = 0; nn < TN; ++nn)
            if (!hflag[nn]) u |= g_rowbits[(size_t)(n0 + nn) * 64 + tid];
        words[tid] = u;
        cnts[tid] = __popc(u);
    }
    __syncthreads();

    if (tid < 64) {
        int base = 0;
        for (int u = 0; u < tid; ++u) base += cnts[u];
        unsigned wv = words[tid];
        int k0 = tid * 32;
        while (wv) {
            int b = __ffs(wv) - 1;
            wv &= wv - 1;
            g_kidx[t * K_DIM + base++] = k0 + b;
        }
    }
    if (tid == 0) {
        int cnt = 0;
        for (int u = 0; u < 64; ++u) cnt += cnts[u];
        int kpad = (cnt + KCHUNK - 1) / KCHUNK * KCHUNK;
        if (kpad == 0) kpad = KCHUNK;
        if (kpad > K_DIM) kpad = K_DIM;
        for (int j = cnt; j < kpad; ++j) g_kidx[t * K_DIM + j] = 0;
        s_cnt = cnt; s_kpad = kpad;
        g_kpad[t] = kpad;
    }
    __syncthreads();

    const int cnt = s_cnt, kpad = s_kpad;
    for (int e = tid; e < kpad * TN; e += blockDim.x) {
        int j  = e / TN;
        int nn = e - j * TN;
        float wv = 0.0f;
        if (j < cnt && !hflag[nn] && (n0 + nn) < N_DIM) {
            int k = g_kidx[t * K_DIM + j];
            size_t off = (size_t)(n0 + nn) * K_DIM + k;
            wv = mask[off] * W[off];
        }
        g_Wp2[((size_t)t * K_DIM + j) * TN + nn] = make_float2(wv, wv);
    }
}

// ---------------------------------------------------------------------------
// 3. Ordered heavy-column list (single block, deterministic).
// ---------------------------------------------------------------------------
__global__ void heavy_list_kernel() {
    const int tid = threadIdx.x;
    const int per = N_DIM / 256;  // 32
    __shared__ int cnt[256];
    __shared__ int off[257];
    int c = 0;
    for (int i = 0; i < per; ++i) c += g_heavyflag[tid * per + i];
    cnt[tid] = c;
    __syncthreads();
    if (tid == 0) {
        off[0] = 0;
        for (int i = 0; i < 256; ++i) off[i + 1] = off[i] + cnt[i];
        g_nheavy = off[256];
    }
    __syncthreads();
    int o = off[tid];
    for (int i = 0; i < per; ++i) {
        int n = tid * per + i;
        if (g_heavyflag[n]) g_heavy[o++] = n;
    }
}

// ---------------------------------------------------------------------------
// 4. Transpose x -> xT[k][m].
// ---------------------------------------------------------------------------
__global__ void transpose_kernel(const float* __restrict__ x,
                                 float* __restrict__ xT) {
    __shared__ float tile[32][33];
    const int k0 = blockIdx.x * 32;
    const int m0 = blockIdx.y * 32;
    const int tx = threadIdx.x, ty = threadIdx.y;   // 32 x 8
    #pragma unroll
    for (int j = 0; j < 32; j += 8)
        tile[ty + j][tx] = x[(size_t)(m0 + ty + j) * K_DIM + k0 + tx];
    __syncthreads();
    #pragma unroll
    for (int j = 0; j < 32; j += 8)
        xT[(size_t)(k0 + ty + j) * M_DIM + m0 + tx] = tile[tx][ty + j];
}

// ---------------------------------------------------------------------------
// 5. Main gather-GEMM over compacted K.
//    Block: 256m x 24n, 128 threads; thread = 8 consecutive m x 6 n.
//    x: 2 LDS.128 per kk ; w: 3 broadcast LDS.128 (pre-splatted) ; 24 FFMA2.
//    3-stage cp.async pipeline, one __syncthreads per chunk.
// ---------------------------------------------------------------------------
__global__ void __launch_bounds__(128)
spmm_kernel(const float* __restrict__ xT,
            const float* __restrict__ bias,
            float* __restrict__ out) {
    const int t    = blockIdx.y;
    const int m0   = blockIdx.x * TM;
    const int n0   = t * TN;
    const int kpad = g_kpad[t];
    const int tid  = threadIdx.x;
    const int tm   = tid & 31;     // rows 8*tm .. 8*tm+7
    const int tn   = tid >> 5;     // cols tn*6 .. tn*6+5

    __shared__ __align__(16) float              s_X[NSTAGE][KCHUNK * TM];  // 24 KB
    __shared__ __align__(16) unsigned long long s_W[NSTAGE][KCHUNK * TN];  // 4.5 KB

    unsigned long long acc[4][6];
    #pragma unroll
    for (int i = 0; i < 4; ++i)
        #pragma unroll
        for (int j = 0; j < 6; ++j) acc[i][j] = 0ull;

    const int*    kidx = g_kidx + t * K_DIM;
    const float2* Wp2  = g_Wp2 + (size_t)t * K_DIM * TN;
    const int nch = kpad >> 3;   // kpad multiple of 8

    // prefetch one KCHUNK into stage s
    auto prefetch = [&](int kc, int s) {
        // x: 8 rows x 64 float4 = 512 float4 ; 4 per thread
        #pragma unroll
        for (int it = 0; it < 4; ++it) {
            int f  = it * 128 + tid;
            int kk = f >> 6;
            int c4 = f & 63;
            const float* src = xT + ((size_t)__ldg(&kidx[kc + kk]) << 14)
                                  + m0 + c4 * 4;
            unsigned dst = (unsigned)__cvta_generic_to_shared(
                &s_X[s][kk * TM + c4 * 4]);
            cpasync16(dst, src);
        }
        // w: 8 rows x 24 float2 = 192 float2 = 96 x 16B ; threads 0..95
        if (tid < 96) {
            int kk = tid / 12, e = tid - kk * 12;   // e: float2-pair index
            const float2* src = Wp2 + (size_t)(kc + kk) * TN + 2 * e;
            unsigned dst = (unsigned)__cvta_generic_to_shared(
                &s_W[s][kk * TN + 2 * e]);
            cpasync16(dst, src);
        }
    };

    prefetch(0, 0);
    cp_commit();
    if (nch > 1) { prefetch(KCHUNK, 1); cp_commit(); }

    for (int c = 0; c < nch; ++c) {
        if (c + 1 < nch) cp_wait<1>(); else cp_wait<0>();
        __syncthreads();

        const float*              sx = &s_X[c % NSTAGE][0];
        const unsigned long long* sw = &s_W[c % NSTAGE][0];
        #pragma unroll
        for (int kk = 0; kk < KCHUNK; ++kk) {
            ulonglong2 xa = *(const ulonglong2*)&sx[kk * TM + 8 * tm];
            ulonglong2 xb = *(const ulonglong2*)&sx[kk * TM + 8 * tm + 4];
            ulonglong2 w01 = *(const ulonglong2*)&sw[kk * TN + 6 * tn];
            ulonglong2 w23 = *(const ulonglong2*)&sw[kk * TN + 6 * tn + 2];
            ulonglong2 w45 = *(const ulonglong2*)&sw[kk * TN + 6 * tn + 4];
            unsigned long long xv[4] = {xa.x, xa.y, xb.x, xb.y};
            unsigned long long wv[6] = {w01.x, w01.y, w23.x, w23.y, w45.x, w45.y};
            #pragma unroll
            for (int i = 0; i < 4; ++i)
                #pragma unroll
                for (int j = 0; j < 6; ++j)
                    fma2(acc[i][j], xv[i], wv[j]);
        }

        if (c + 2 < nch) { prefetch((c + 2) * KCHUNK, (c + 2) % NSTAGE); cp_commit(); }
    }

    // ---- epilogue ---------------------------------------------------------
    float bb[6];
    #pragma unroll
    for (int j = 0; j < 6; ++j) {
        int n = n0 + tn * 6 + j;
        bb[j] = (n < N_DIM) ? bias[n] : 0.0f;
    }
    #pragma unroll
    for (int i = 0; i < 4; ++i) {
        float lo[6], hi[6];
        #pragma unroll
        for (int j = 0; j < 6; ++j) unpack2(acc[i][j], lo[j], hi[j]);
        int r0 = m0 + 8 * tm + 2 * i;          // even row of the pair
        float* d0 = out + (size_t)r0 * N_DIM + n0 + tn * 6;
        float* d1 = d0 + N_DIM;
        #pragma unroll
        for (int j = 0; j < 3; ++j) {
            int n = n0 + tn * 6 + 2 * j;
            if (n + 1 < N_DIM) {
                *(float2*)(d0 + 2 * j) = make_float2(lo[2*j] + bb[2*j], lo[2*j+1] + bb[2*j+1]);
                *(float2*)(d1 + 2 * j) = make_float2(hi[2*j] + bb[2*j], hi[2*j+1] + bb[2*j+1]);
            } else if (n < N_DIM) {
                d0[2 * j] = lo[2 * j] + bb[2 * j];
                d1[2 * j] = hi[2 * j] + bb[2 * j];
            }
        }
    }
}

// ---------------------------------------------------------------------------
// 6. Heavy columns: full dense dot per (column, row-pair), overwrites output.
// ---------------------------------------------------------------------------
__global__ void dense_cols_kernel(const float* __restrict__ x,
                                  const float* __restrict__ W,
                                  const float* __restrict__ mask,
                                  const float* __restrict__ bias,
                                  float* __restrict__ out) {
    const int nh = g_nheavy;
    if (nh == 0) return;
    const int wflat = (blockIdx.x * blockDim.x + threadIdx.x) >> 5;  // 0..8191
    const int lane  = threadIdx.x & 31;
    const int units_per_col = M_DIM / 2;
    const int total = nh * units_per_col;
    for (int u = wflat; u < total; u += 8192) {
        int c   = g_heavy[u / units_per_col];
        int seg = u % units_per_col;
        int r0  = seg * 2;
        const float* wr = W    + (size_t)c * K_DIM;
        const float* mr = mask + (size_t)c * K_DIM;
        const float* x0 = x + (size_t)r0 * K_DIM;
        float s0 = 0.0f, s1 = 0.0f;
        #pragma unroll 4
        for (int k = lane; k < K_DIM; k += 32) {
            float wv = mr[k] * wr[k];
            s0 += x0[k] * wv;
            s1 += x0[K_DIM + k] * wv;
        }
        #pragma unroll
        for (int d = 16; d; d >>= 1) {
            s0 += __shfl_xor_sync(0xffffffffu, s0, d);
            s1 += __shfl_xor_sync(0xffffffffu, s1, d);
        }
        if (lane == 0) {
            float b = bias[c];
            out[(size_t)r0 * N_DIM + c]       = s0 + b;
            out[(size_t)(r0 + 1) * N_DIM + c] = s1 + b;
        }
    }
}

// ---------------------------------------------------------------------------
extern "C" void kernel_launch(void* const* d_in, const int* in_sizes, int n_in,
                              void* d_out, int out_size) {
    const float* x    = (const float*)d_in[0];  // [16384, 2048]
    const float* W    = (const float*)d_in[1];  // [8192, 2048]
    const float* bias = (const float*)d_in[2];  // [8192]
    const float* mask = (const float*)d_in[3];  // [8192, 2048]
    float* out = (float*)d_out;                 // [16384, 8192]

    float* xT = nullptr;
    cudaGetSymbolAddress((void**)&xT, g_xT);

    rowscan_kernel<<<N_DIM / 8, 256>>>(mask);
    tile_pack_kernel<<<NTILES, 256>>>(W, mask);
    heavy_list_kernel<<<1, 256>>>();
    {
        dim3 tb(32, 8);
        dim3 tg(K_DIM / 32, M_DIM / 32);
        transpose_kernel<<<tg, tb>>>(x, xT);
    }
    {
        dim3 grid(M_DIM / TM, NTILES);
        spmm_kernel<<<grid, 128>>>(xT, bias, out);
    }
    dense_cols_kernel<<<1024, 256>>>(x, W, mask, bias, out);
}

// round 5
// speedup vs baseline: 1.0814x; 1.0814x over previous
#include <cuda_runtime.h>

// y[m,n] = sum_k x[m,k] * (mask[n,k]*W[n,k]) + b[n]
// M=16384, K=2048, N=8192, fp32.
//
// Pipeline:
//  1. rowscan:    per output row n, 64-word k-bitmask + heavy flag (>=256 nnz)
//  2. tile_pack:  per 24-wide n-tile, union of non-heavy rows' bitmasks ->
//                 ordered k index list + packed PRE-SPLATTED weight panel
//  3. heavy_list: deterministic ordered list of heavy columns
//  4. transpose:  xT[k][m]  (spmm gather becomes coalesced)
//  5. spmm:       gather GEMM over compacted K; 3-stage cp.async pipeline,
//                 one bar/chunk, f32x2 over m-pairs, conflict-free LDS.128
//                 (16B lane stride: rows 4*tm+{0..3} and 128+4*tm+{0..3})
//  6. dense_cols: recompute heavy columns densely, overwrite their output

#define M_DIM 16384
#define K_DIM 2048
#define N_DIM 8192
#define TN 24
#define NTILES ((N_DIM + TN - 1) / TN)   // 342
#define TM 256
#define KCHUNK 8
#define NSTAGE 3
#define HEAVY_THRESH 256

// Static scratch (allocations are forbidden).
__device__ unsigned g_rowbits[(size_t)N_DIM * 64];            // 2 MB
__device__ int      g_heavyflag[N_DIM];
__device__ int      g_heavy[N_DIM];
__device__ int      g_nheavy;
__device__ int      g_kidx[NTILES * K_DIM];                   // 2.8 MB
__device__ int      g_kpad[NTILES];
__device__ float2   g_Wp2[(size_t)NTILES * K_DIM * TN];       // 134 MB, splatted
__device__ float    g_xT[(size_t)K_DIM * M_DIM];              // 128 MB

// ---------------------------------------------------------------------------
// helpers
// ---------------------------------------------------------------------------
__device__ __forceinline__ void fma2(unsigned long long& acc,
                                     unsigned long long a,
                                     unsigned long long b) {
    asm("fma.rn.f32x2 %0, %1, %2, %0;" : "+l"(acc) : "l"(a), "l"(b));
}
__device__ __forceinline__ void unpack2(unsigned long long a, float& lo, float& hi) {
    asm("mov.b64 {%0, %1}, %2;" : "=f"(lo), "=f"(hi) : "l"(a));
}
__device__ __forceinline__ void cpasync16(unsigned dst, const void* src) {
    asm volatile("cp.async.cg.shared.global [%0], [%1], 16;" :: "r"(dst), "l"(src));
}
__device__ __forceinline__ void cp_commit() { asm volatile("cp.async.commit_group;"); }
template <int N>
__device__ __forceinline__ void cp_wait() { asm volatile("cp.async.wait_group %0;" :: "n"(N)); }

// ---------------------------------------------------------------------------
// 1. Per-row bitmask + heavy flag. One warp per output row.
// ---------------------------------------------------------------------------
__global__ void rowscan_kernel(const float* __restrict__ mask) {
    int warp = (blockIdx.x * blockDim.x + threadIdx.x) >> 5;
    int lane = threadIdx.x & 31;
    if (warp >= N_DIM) return;
    const float* row = mask + (size_t)warp * K_DIM;
    int cnt = 0;
    #pragma unroll 8
    for (int w = 0; w < K_DIM / 32; ++w) {
        float v = row[w * 32 + lane];
        unsigned b = __ballot_sync(0xffffffffu, v != 0.0f);
        if (lane == 0) g_rowbits[(size_t)warp * 64 + w] = b;
        cnt += __popc(b);
    }
    if (lane == 0) g_heavyflag[warp] = (cnt >= HEAVY_THRESH) ? 1 : 0;
}

// ---------------------------------------------------------------------------
// 2. Per n-tile: union bitmask (excluding heavy rows), ordered compaction,
//    packed pre-splatted masked weights.
// ---------------------------------------------------------------------------
__global__ void tile_pack_kernel(const float* __restrict__ W,
                                 const float* __restrict__ mask) {
    const int t = blockIdx.x, n0 = t * TN, tid = threadIdx.x;
    __shared__ unsigned words[64];
    __shared__ int cnts[64];
    __shared__ int hflag[TN];
    __shared__ int s_cnt, s_kpad;

    if (tid < TN)
        hflag[tid] = (n0 + tid < N_DIM) ? g_heavyflag[n0 + tid] : 1;
    __syncthreads();

    if (tid < 64) {
        unsigned u = 0;
        #pragma unroll 4
        for (int nn = 0; nn < TN; ++nn)
            if (!hflag[nn]) u |= g_rowbits[(size_t)(n0 + nn) * 64 + tid];
        words[tid] = u;
        cnts[tid] = __popc(u);
    }
    __syncthreads();

    if (tid < 64) {
        int base = 0;
        for (int u = 0; u < tid; ++u) base += cnts[u];
        unsigned wv = words[tid];
        int k0 = tid * 32;
        while (wv) {
            int b = __ffs(wv) - 1;
            wv &= wv - 1;
            g_kidx[t * K_DIM + base++] = k0 + b;
        }
    }
    if (tid == 0) {
        int cnt = 0;
        for (int u = 0; u < 64; ++u) cnt += cnts[u];
        int kpad = (cnt + KCHUNK - 1) / KCHUNK * KCHUNK;
        if (kpad == 0) kpad = KCHUNK;
        if (kpad > K_DIM) kpad = K_DIM;
        for (int j = cnt; j < kpad; ++j) g_kidx[t * K_DIM + j] = 0;
        s_cnt = cnt; s_kpad = kpad;
        g_kpad[t] = kpad;
    }
    __syncthreads();

    const int cnt = s_cnt, kpad = s_kpad;
    for (int e = tid; e < kpad * TN; e += blockDim.x) {
        int j  = e / TN;
        int nn = e - j * TN;
        float wv = 0.0f;
        if (j < cnt && !hflag[nn] && (n0 + nn) < N_DIM) {
            int k = g_kidx[t * K_DIM + j];
            size_t off = (size_t)(n0 + nn) * K_DIM + k;
            wv = mask[off] * W[off];
        }
        g_Wp2[((size_t)t * K_DIM + j) * TN + nn] = make_float2(wv, wv);
    }
}

// ---------------------------------------------------------------------------
// 3. Ordered heavy-column list (single block, deterministic).
// ---------------------------------------------------------------------------
__global__ void heavy_list_kernel() {
    const int tid = threadIdx.x;
    const int per = N_DIM / 256;  // 32
    __shared__ int cnt[256];
    __shared__ int off[257];
    int c = 0;
    for (int i = 0; i < per; ++i) c += g_heavyflag[tid * per + i];
    cnt[tid] = c;
    __syncthreads();
    if (tid == 0) {
        off[0] = 0;
        for (int i = 0; i < 256; ++i) off[i + 1] = off[i] + cnt[i];
        g_nheavy = off[256];
    }
    __syncthreads();
    int o = off[tid];
    for (int i = 0; i < per; ++i) {
        int n = tid * per + i;
        if (g_heavyflag[n]) g_heavy[o++] = n;
    }
}

// ---------------------------------------------------------------------------
// 4. Transpose x -> xT[k][m].
// ---------------------------------------------------------------------------
__global__ void transpose_kernel(const float* __restrict__ x,
                                 float* __restrict__ xT) {
    __shared__ float tile[32][33];
    const int k0 = blockIdx.x * 32;
    const int m0 = blockIdx.y * 32;
    const int tx = threadIdx.x, ty = threadIdx.y;   // 32 x 8
    #pragma unroll
    for (int j = 0; j < 32; j += 8)
        tile[ty + j][tx] = x[(size_t)(m0 + ty + j) * K_DIM + k0 + tx];
    __syncthreads();
    #pragma unroll
    for (int j = 0; j < 32; j += 8)
        xT[(size_t)(k0 + ty + j) * M_DIM + m0 + tx] = tile[tx][ty + j];
}

// ---------------------------------------------------------------------------
// 5. Main gather-GEMM over compacted K.
//    Block: 256m x 24n, 128 threads; thread = rows 4*tm+{0..3} and
//    128+4*tm+{0..3} (16B lane stride -> conflict-free LDS.128), cols tn*6+..5.
// ---------------------------------------------------------------------------
__global__ void __launch_bounds__(128)
spmm_kernel(const float* __restrict__ xT,
            const float* __restrict__ bias,
            float* __restrict__ out) {
    const int t    = blockIdx.y;
    const int m0   = blockIdx.x * TM;
    const int n0   = t * TN;
    const int kpad = g_kpad[t];
    const int tid  = threadIdx.x;
    const int tm   = tid & 31;     // quad base: rows 4*tm.., and +128
    const int tn   = tid >> 5;     // cols tn*6 .. tn*6+5

    __shared__ __align__(16) float              s_X[NSTAGE][KCHUNK * TM];  // 24 KB
    __shared__ __align__(16) unsigned long long s_W[NSTAGE][KCHUNK * TN];  // 4.5 KB

    unsigned long long acc[4][6];
    #pragma unroll
    for (int i = 0; i < 4; ++i)
        #pragma unroll
        for (int j = 0; j < 6; ++j) acc[i][j] = 0ull;

    const int*    kidx = g_kidx + t * K_DIM;
    const float2* Wp2  = g_Wp2 + (size_t)t * K_DIM * TN;
    const int nch = kpad >> 3;   // kpad multiple of 8

    // prefetch one KCHUNK into stage s
    auto prefetch = [&](int kc, int s) {
        // x: 8 rows x 64 float4 = 512 float4 ; 4 per thread
        #pragma unroll
        for (int it = 0; it < 4; ++it) {
            int f  = it * 128 + tid;
            int kk = f >> 6;
            int c4 = f & 63;
            const float* src = xT + ((size_t)__ldg(&kidx[kc + kk]) << 14)
                                  + m0 + c4 * 4;
            unsigned dst = (unsigned)__cvta_generic_to_shared(
                &s_X[s][kk * TM + c4 * 4]);
            cpasync16(dst, src);
        }
        // w: 8 rows x 24 float2 = 192 float2 = 96 x 16B ; threads 0..95
        if (tid < 96) {
            int kk = tid / 12, e = tid - kk * 12;   // e: float2-pair index
            const float2* src = Wp2 + (size_t)(kc + kk) * TN + 2 * e;
            unsigned dst = (unsigned)__cvta_generic_to_shared(
                &s_W[s][kk * TN + 2 * e]);
            cpasync16(dst, src);
        }
    };

    prefetch(0, 0);
    cp_commit();
    if (nch > 1) { prefetch(KCHUNK, 1); cp_commit(); }

    for (int c = 0; c < nch; ++c) {
        if (c + 1 < nch) cp_wait<1>(); else cp_wait<0>();
        __syncthreads();

        const float*              sx = &s_X[c % NSTAGE][0];
        const unsigned long long* sw = &s_W[c % NSTAGE][0];
        #pragma unroll
        for (int kk = 0; kk < KCHUNK; ++kk) {
            // conflict-free: 16B lane stride
            ulonglong2 xa = *(const ulonglong2*)&sx[kk * TM + 4 * tm];
            ulonglong2 xb = *(const ulonglong2*)&sx[kk * TM + 128 + 4 * tm];
            ulonglong2 w01 = *(const ulonglong2*)&sw[kk * TN + 6 * tn];
            ulonglong2 w23 = *(const ulonglong2*)&sw[kk * TN + 6 * tn + 2];
            ulonglong2 w45 = *(const ulonglong2*)&sw[kk * TN + 6 * tn + 4];
            unsigned long long xv[4] = {xa.x, xa.y, xb.x, xb.y};
            unsigned long long wv[6] = {w01.x, w01.y, w23.x, w23.y, w45.x, w45.y};
            #pragma unroll
            for (int i = 0; i < 4; ++i)
                #pragma unroll
                for (int j = 0; j < 6; ++j)
                    fma2(acc[i][j], xv[i], wv[j]);
        }

        if (c + 2 < nch) { prefetch((c + 2) * KCHUNK, (c + 2) % NSTAGE); cp_commit(); }
    }

    // ---- epilogue ---------------------------------------------------------
    float bb[6];
    #pragma unroll
    for (int j = 0; j < 6; ++j) {
        int n = n0 + tn * 6 + j;
        bb[j] = (n < N_DIM) ? bias[n] : 0.0f;
    }
    #pragma unroll
    for (int i = 0; i < 4; ++i) {
        float lo[6], hi[6];
        #pragma unroll
        for (int j = 0; j < 6; ++j) unpack2(acc[i][j], lo[j], hi[j]);
        // i=0: rows 4tm,4tm+1 ; i=1: 4tm+2,4tm+3 ; i=2: +128 ; i=3: +130
        int r0 = m0 + 4 * tm + (i & 1) * 2 + (i >> 1) * 128;
        float* d0 = out + (size_t)r0 * N_DIM + n0 + tn * 6;
        float* d1 = d0 + N_DIM;
        #pragma unroll
        for (int j = 0; j < 3; ++j) {
            int n = n0 + tn * 6 + 2 * j;
            if (n + 1 < N_DIM) {
                *(float2*)(d0 + 2 * j) = make_float2(lo[2*j] + bb[2*j], lo[2*j+1] + bb[2*j+1]);
                *(float2*)(d1 + 2 * j) = make_float2(hi[2*j] + bb[2*j], hi[2*j+1] + bb[2*j+1]);
            } else if (n < N_DIM) {
                d0[2 * j] = lo[2 * j] + bb[2 * j];
                d1[2 * j] = hi[2 * j] + bb[2 * j];
            }
        }
    }
}

// ---------------------------------------------------------------------------
// 6. Heavy columns: full dense dot per (column, row-pair), overwrites output.
// ---------------------------------------------------------------------------
__global__ void dense_cols_kernel(const float* __restrict__ x,
                                  const float* __restrict__ W,
                                  const float* __restrict__ mask,
                                  const float* __restrict__ bias,
                                  float* __restrict__ out) {
    const int nh = g_nheavy;
    if (nh == 0) return;
    const int wflat = (blockIdx.x * blockDim.x + threadIdx.x) >> 5;  // 0..8191
    const int lane  = threadIdx.x & 31;
    const int units_per_col = M_DIM / 2;
    const int total = nh * units_per_col;
    for (int u = wflat; u < total; u += 8192) {
        int c   = g_heavy[u / units_per_col];
        int seg = u % units_per_col;
        int r0  = seg * 2;
        const float* wr = W    + (size_t)c * K_DIM;
        const float* mr = mask + (size_t)c * K_DIM;
        const float* x0 = x + (size_t)r0 * K_DIM;
        float s0 = 0.0f, s1 = 0.0f;
        #pragma unroll 4
        for (int k = lane; k < K_DIM; k += 32) {
            float wv = mr[k] * wr[k];
            s0 += x0[k] * wv;
            s1 += x0[K_DIM + k] * wv;
        }
        #pragma unroll
        for (int d = 16; d; d >>= 1) {
            s0 += __shfl_xor_sync(0xffffffffu, s0, d);
            s1 += __shfl_xor_sync(0xffffffffu, s1, d);
        }
        if (lane == 0) {
            float b = bias[c];
            out[(size_t)r0 * N_DIM + c]       = s0 + b;
            out[(size_t)(r0 + 1) * N_DIM + c] = s1 + b;
        }
    }
}

// ---------------------------------------------------------------------------
extern "C" void kernel_launch(void* const* d_in, const int* in_sizes, int n_in,
                              void* d_out, int out_size) {
    const float* x    = (const float*)d_in[0];  // [16384, 2048]
    const float* W    = (const float*)d_in[1];  // [8192, 2048]
    const float* bias = (const float*)d_in[2];  // [8192]
    const float* mask = (const float*)d_in[3];  // [8192, 2048]
    float* out = (float*)d_out;                 // [16384, 8192]

    float* xT = nullptr;
    cudaGetSymbolAddress((void**)&xT, g_xT);

    rowscan_kernel<<<N_DIM / 8, 256>>>(mask);
    tile_pack_kernel<<<NTILES, 256>>>(W, mask);
    heavy_list_kernel<<<1, 256>>>();
    {
        dim3 tb(32, 8);
        dim3 tg(K_DIM / 32, M_DIM / 32);
        transpose_kernel<<<tg, tb>>>(x, xT);
    }
    {
        dim3 grid(M_DIM / TM, NTILES);
        spmm_kernel<<<grid, 128>>>(xT, bias, out);
    }
    dense_cols_kernel<<<1024, 256>>>(x, W, mask, bias, out);
}